// round 1
// baseline (speedup 1.0000x reference)
#include <cuda_runtime.h>
#include <math.h>

// Problem constants (fixed by the dataset)
#define MM 512
#define NN 256
#define DD 64
#define EPSV 1e-6f
#define INFV 1e30f

// ---------------- device scratch (no allocations allowed) ----------------
__device__ float g_dists[MM * NN];          // 512 KB  d[m][n]
__device__ float g_qT[NN * (NN + 1)];       // 263 KB  qT[nb][i] = q[i][nb]
__device__ float g_p[NN + 1];               // reachability
__device__ float g_w[NN * NN];              // 256 KB  w[n][nb] (0 where not an edge)
__device__ float g_fw[NN];                  // final weights p_back[N][:]
__device__ float g_C[MM * NN];              // 512 KB  DP table
__device__ int   g_prog[NN * 32];           // per-column progress flag, 128B stride

// ---------------- stage 0: reset flags (graph replays must be deterministic) ----
__global__ void init_kernel() {
    int t = blockIdx.x * 256 + threadIdx.x;
    if (t < NN * 32) g_prog[t] = -1;
}

// ---------------- stage 1: pairwise L2 distances (exact diff form) ----------
// Tile: 32 m x 64 n per CTA, 256 threads, 8 outputs/thread.
__global__ void __launch_bounds__(256) dist_kernel(const float* __restrict__ x,
                                                   const float* __restrict__ y) {
    __shared__ float xs[32][DD + 1];
    __shared__ float ys[64][DD + 1];
    int m0 = blockIdx.x * 32;
    int n0 = blockIdx.y * 64;
    int t = threadIdx.x;

    for (int i = t; i < 32 * DD; i += 256) xs[i / DD][i % DD] = x[(m0 + i / DD) * DD + i % DD];
    for (int i = t; i < 64 * DD; i += 256) ys[i / DD][i % DD] = y[(n0 + i / DD) * DD + i % DD];
    __syncthreads();

    int tn = t & 63;       // n within tile
    int tm = t >> 6;       // 0..3, each covers 8 m rows
    float acc[8];
#pragma unroll
    for (int r = 0; r < 8; r++) acc[r] = 0.f;

    for (int k = 0; k < DD; k++) {
        float yv = ys[tn][k];
#pragma unroll
        for (int r = 0; r < 8; r++) {
            float d = xs[tm * 8 + r][k] - yv;
            acc[r] = fmaf(d, d, acc[r]);
        }
    }
#pragma unroll
    for (int r = 0; r < 8; r++)
        g_dists[(m0 + tm * 8 + r) * NN + (n0 + tn)] = sqrtf(acc[r]);
}

// ---------------- stage 2a: transpose q for coalesced scan ----------------
__global__ void transpose_q(const float* __restrict__ q) {
    int idx = blockIdx.x * 256 + threadIdx.x;
    if (idx < NN * (NN + 1)) {
        int nb = idx / (NN + 1);
        int i  = idx % (NN + 1);
        g_qT[idx] = q[i * NN + nb];
    }
}

// ---------------- stage 2b: sequential reachability scan ------------------
// p := p + p[nb] * q[:, nb] for nb = 0..N-1, exactly the reference order.
__global__ void __launch_bounds__(320) scan_kernel() {
    __shared__ float ps[NN + 1];
    int t = threadIdx.x;
    bool act = (t <= NN);
    if (act) ps[t] = (t == 0) ? 1.f : 0.f;
    __syncthreads();

    float qv = act ? g_qT[t] : 0.f;   // column 0
    for (int nb = 0; nb < NN; nb++) {
        float qnext = (act && nb + 1 < NN) ? g_qT[(nb + 1) * (NN + 1) + t] : 0.f;
        float pnb = ps[nb];
        __syncthreads();
        if (act) ps[t] = ps[t] + pnb * qv;
        __syncthreads();
        qv = qnext;
    }
    if (act) g_p[t] = ps[t];
}

// ---------------- stage 3: mixing weights + terminal weights ---------------
__global__ void weights_kernel(const float* __restrict__ q) {
    int idx = blockIdx.x * 256 + threadIdx.x;  // N*N threads
    int n  = idx >> 8;
    int nb = idx & 255;
    float pb = g_p[nb] * q[n * NN + nb] / (g_p[n] + EPSV);
    g_w[idx] = (nb < n && pb > 0.f) ? pb : 0.f;
    if (n == 0) {
        float pbf = g_p[nb] * q[NN * NN + nb] / (g_p[NN] + EPSV);
        g_fw[nb] = pbf;
    }
}

// ---------------- stage 4: the wavefront DP pipeline -----------------------
// One persistent warp per column n. Cbar row, w row, and C[m-1][:] live in
// registers. Cross-column sync via release/acquire progress flags in L2.
__global__ void __launch_bounds__(256, 1) dp_kernel() {
    int lane = threadIdx.x & 31;
    int wid  = threadIdx.x >> 5;
    int n = blockIdx.x * 8 + wid;

    if (n == 0) {
        // C[m][0] = d[m][0] + C[m-1][0] ; Cbar[m][0] = INF (never consumed)
        if (lane == 0) {
            float run = 0.f;
            for (int m = 0; m < MM; m++) {
                run += g_dists[m * NN];
                g_C[m * NN] = run;
                asm volatile("st.release.gpu.b32 [%0], %1;"
                             :: "l"(&g_prog[0]), "r"(m) : "memory");
            }
        }
        return;
    }

    float wreg[8], Breg[8], Pprev[8];
#pragma unroll
    for (int j = 0; j < 8; j++) {
        wreg[j]  = g_w[n * NN + lane + 32 * j];
        Breg[j]  = INFV;   // Cbar[m-1][n][nb] starts as INF (m=0 case)
        Pprev[j] = INFV;   // C[m-1][nb]       starts as INF (m=0 case)
    }

    int* flag = &g_prog[(n - 1) * 32];

    for (int m = 0; m < MM; m++) {
        // wait for column n-1 to finish row m (transitively: all nb < n done)
        int v;
        do {
            asm volatile("ld.acquire.gpu.b32 %0, [%1];" : "=r"(v) : "l"(flag) : "memory");
        } while (v < m);

        float dmn = g_dists[m * NN + n];
        const float* Crow = &g_C[m * NN];
        float acc = 0.f;
#pragma unroll
        for (int j = 0; j < 8; j++) {
            int idx = lane + 32 * j;
            if (idx < n) {
                float cc = Crow[idx];
                float mn = fminf(cc, fminf(Pprev[j], Breg[j]));
                float cb = dmn + mn;
                if (wreg[j] > 0.f) {      // E mask: only real edges update Cbar / sum
                    acc += wreg[j] * cb;
                    Breg[j] = cb;
                }
                Pprev[j] = cc;
            }
        }
        // warp sum
#pragma unroll
        for (int off = 16; off; off >>= 1)
            acc += __shfl_xor_sync(0xffffffffu, acc, off);

        if (lane == 0) {
            g_C[m * NN + n] = acc;
            asm volatile("st.release.gpu.b32 [%0], %1;"
                         :: "l"(&g_prog[n * 32]), "r"(m) : "memory");
        }
    }
}

// ---------------- stage 5: terminal expectation ----------------------------
__global__ void __launch_bounds__(256) final_kernel(float* __restrict__ out) {
    int t = threadIdx.x;
    float v = g_fw[t] * g_C[(MM - 1) * NN + t];
#pragma unroll
    for (int off = 16; off; off >>= 1) v += __shfl_xor_sync(0xffffffffu, v, off);
    __shared__ float s[8];
    if ((t & 31) == 0) s[t >> 5] = v;
    __syncthreads();
    if (t < 8) {
        float z = s[t];
#pragma unroll
        for (int off = 4; off; off >>= 1) z += __shfl_xor_sync(0xffu, z, off);
        if (t == 0) out[0] = z;
    }
}

// ---------------- launch ----------------------------------------------------
extern "C" void kernel_launch(void* const* d_in, const int* in_sizes, int n_in,
                              void* d_out, int out_size) {
    // Identify inputs by element count (x: 512*64, y: 256*64, q: 257*256)
    const float* x = nullptr;
    const float* y = nullptr;
    const float* q = nullptr;
    for (int i = 0; i < n_in; i++) {
        if (in_sizes[i] == MM * DD)            x = (const float*)d_in[i];
        else if (in_sizes[i] == NN * DD)       y = (const float*)d_in[i];
        else if (in_sizes[i] == (NN + 1) * NN) q = (const float*)d_in[i];
    }
    float* out = (float*)d_out;

    init_kernel<<<32, 256>>>();

    dim3 dg(MM / 32, NN / 64);
    dist_kernel<<<dg, 256>>>(x, y);

    transpose_q<<<(NN * (NN + 1) + 255) / 256, 256>>>(q);
    scan_kernel<<<1, 320>>>();
    weights_kernel<<<NN * NN / 256, 256>>>(q);

    dp_kernel<<<32, 256>>>();   // 256 persistent warps, one per column

    final_kernel<<<1, 256>>>(out);
}

// round 4
// speedup vs baseline: 2.0902x; 2.0902x over previous
#include <cuda_runtime.h>
#include <math.h>

// Problem constants (fixed by the dataset)
#define MM 512
#define NN 256
#define DD 64
#define EPSV 1e-6f
#define INFV 1e30f
#define SENTU 0xFFC00001u   // NaN payload; never produced by the DP arithmetic

// ---------------- device scratch (no allocations allowed) ----------------
__device__ float g_dists[MM * NN];          // d[m][n]
__device__ float g_qT[NN * (NN + 1)];       // qT[nb][i] = q[i][nb]
__device__ float g_p[NN + 1];               // reachability
__device__ float g_w[NN * NN];              // w[n][nb] (0 where not an edge)
__device__ float g_fw[NN];                  // final weights p_back[N][:]
__device__ float g_C[MM * NN];              // DP table (sentinel-initialized)

// ---------------- tiny asm helpers ----------------
__device__ __forceinline__ unsigned ldcg_u32(const float* p) {
    unsigned v;
    asm volatile("ld.global.cg.b32 %0, [%1];" : "=r"(v) : "l"(p));
    return v;
}
__device__ __forceinline__ void stcg_f32(float* p, float v) {
    asm volatile("st.global.cg.b32 [%0], %1;" :: "l"(p), "f"(v));
}

// ---------------- stage 0: sentinel-fill C (every launch; graph-replay safe) ----
__global__ void init_kernel() {
    int t = blockIdx.x * 256 + threadIdx.x;
    if (t < MM * NN) g_C[t] = __uint_as_float(SENTU);
}

// ---------------- stage 1: pairwise L2 distances ----------
__global__ void __launch_bounds__(256) dist_kernel(const float* __restrict__ x,
                                                   const float* __restrict__ y) {
    __shared__ float xs[32][DD + 1];
    __shared__ float ys[64][DD + 1];
    int m0 = blockIdx.x * 32;
    int n0 = blockIdx.y * 64;
    int t = threadIdx.x;

    for (int i = t; i < 32 * DD; i += 256) xs[i / DD][i % DD] = x[(m0 + i / DD) * DD + i % DD];
    for (int i = t; i < 64 * DD; i += 256) ys[i / DD][i % DD] = y[(n0 + i / DD) * DD + i % DD];
    __syncthreads();

    int tn = t & 63;
    int tm = t >> 6;
    float acc[8];
#pragma unroll
    for (int r = 0; r < 8; r++) acc[r] = 0.f;

    for (int k = 0; k < DD; k++) {
        float yv = ys[tn][k];
#pragma unroll
        for (int r = 0; r < 8; r++) {
            float d = xs[tm * 8 + r][k] - yv;
            acc[r] = fmaf(d, d, acc[r]);
        }
    }
#pragma unroll
    for (int r = 0; r < 8; r++)
        g_dists[(m0 + tm * 8 + r) * NN + (n0 + tn)] = sqrtf(acc[r]);
}

// ---------------- stage 2a: transpose q for coalesced scan ----------------
__global__ void transpose_q(const float* __restrict__ q) {
    int idx = blockIdx.x * 256 + threadIdx.x;
    if (idx < NN * (NN + 1)) {
        int nb = idx / (NN + 1);
        int i  = idx % (NN + 1);
        g_qT[idx] = q[i * NN + nb];
    }
}

// ---------------- stage 2b: reachability scan, prefetch depth 4 ------------
__global__ void __launch_bounds__(320) scan_kernel() {
    __shared__ float ps[NN + 1];
    int t = threadIdx.x;
    bool act = (t <= NN);
    if (act) ps[t] = (t == 0) ? 1.f : 0.f;
    __syncthreads();

    float q0 = act ? g_qT[0 * (NN + 1) + t] : 0.f;
    float q1 = act ? g_qT[1 * (NN + 1) + t] : 0.f;
    float q2 = act ? g_qT[2 * (NN + 1) + t] : 0.f;
    float q3 = act ? g_qT[3 * (NN + 1) + t] : 0.f;

    for (int nb = 0; nb < NN; nb += 4) {
        float t0 = (act && nb + 4 < NN) ? g_qT[(nb + 4) * (NN + 1) + t] : 0.f;
        float t1 = (act && nb + 5 < NN) ? g_qT[(nb + 5) * (NN + 1) + t] : 0.f;
        float t2 = (act && nb + 6 < NN) ? g_qT[(nb + 6) * (NN + 1) + t] : 0.f;
        float t3 = (act && nb + 7 < NN) ? g_qT[(nb + 7) * (NN + 1) + t] : 0.f;

        float pnb;
        pnb = ps[nb + 0]; __syncthreads(); if (act) ps[t] += pnb * q0; __syncthreads();
        pnb = ps[nb + 1]; __syncthreads(); if (act) ps[t] += pnb * q1; __syncthreads();
        pnb = ps[nb + 2]; __syncthreads(); if (act) ps[t] += pnb * q2; __syncthreads();
        pnb = ps[nb + 3]; __syncthreads(); if (act) ps[t] += pnb * q3; __syncthreads();

        q0 = t0; q1 = t1; q2 = t2; q3 = t3;
    }
    if (act) g_p[t] = ps[t];
}

// ---------------- stage 3: mixing weights + terminal weights ---------------
__global__ void weights_kernel(const float* __restrict__ q) {
    int idx = blockIdx.x * 256 + threadIdx.x;  // N*N threads
    int n  = idx >> 8;
    int nb = idx & 255;
    float pb = g_p[nb] * q[n * NN + nb] / (g_p[n] + EPSV);
    g_w[idx] = (nb < n && pb > 0.f) ? pb : 0.f;
    if (n == 0) {
        g_fw[nb] = g_p[nb] * q[NN * NN + nb] / (g_p[NN] + EPSV);
    }
}

// ---------------- stage 4: fence-free wavefront DP -------------------------
// One warp = one CTA = one column. All handoffs via sentinel-valued g_C in L2
// (st.cg / ld.cg). Poll loops back off with __nanosleep -> guaranteed forward
// progress. CRITICAL: the verify-retry only waits on lanes with idx < n —
// cells owned by strictly earlier columns. Waiting on any lane with idx >= n
// is a cyclic dependency (deadlock), which is what broke round 3.
__global__ void __launch_bounds__(32, 32) dp_kernel() {
    const int lane = threadIdx.x;
    const int n = blockIdx.x;

    if (n == 0) {
        // column 0: C[m][0] = running sum of d[m][0] via warp inclusive scan
        float run = 0.f;
        for (int mb = 0; mb < MM; mb += 32) {
            float dv = g_dists[(mb + lane) * NN];
#pragma unroll
            for (int off = 1; off < 32; off <<= 1) {
                float t = __shfl_up_sync(0xffffffffu, dv, off);
                if (lane >= off) dv += t;
            }
            float val = run + dv;
            stcg_f32(&g_C[(mb + lane) * NN], val);
            run = __shfl_sync(0xffffffffu, val, 31);
        }
        return;
    }

    float wreg[8], Breg[8], Pprev[8];
#pragma unroll
    for (int j = 0; j < 8; j++) {
        int idx = j * 32 + lane;
        wreg[j]  = (idx < n) ? g_w[n * NN + idx] : 0.f;
        Breg[j]  = INFV;
        Pprev[j] = INFV;
    }

    const int jmax = (n - 1) >> 5;   // highest chunk containing a needed column

    for (int m = 0; m < MM; m++) {
        float dmn = __ldg(&g_dists[m * NN + n]);
        const float* Crow = &g_C[m * NN];

        // speculative loads of all needed chunks (issued before the poll)
        unsigned cu[8];
#pragma unroll
        for (int j = 0; j < 8; j++)
            if (j <= jmax) cu[j] = ldcg_u32(&Crow[j * 32 + lane]);

        // poll the immediate predecessor column (scalar broadcast load)
        const float* paddr = &Crow[n - 1];
        unsigned pv = ldcg_u32(paddr);
        while (pv == SENTU) {
            __nanosleep(40);
            pv = ldcg_u32(paddr);
        }

        // verify-retry ONLY lanes whose cells belong to columns < n
        for (;;) {
            int again = 0;
#pragma unroll
            for (int j = 0; j < 8; j++) {
                if (j <= jmax) {
                    bool need = ((j * 32 + lane) < n) && (cu[j] == SENTU);
                    if (__any_sync(0xffffffffu, need)) {
                        if (need) cu[j] = ldcg_u32(&Crow[j * 32 + lane]);
                        again = 1;
                    }
                }
            }
            if (!again) break;
            __nanosleep(20);
        }

        // compute cell (m, n)
        float acc = 0.f;
#pragma unroll
        for (int j = 0; j < 8; j++) {
            int idx = j * 32 + lane;
            if (idx < n) {
                float cc = __uint_as_float(cu[j]);
                float mn = fminf(cc, fminf(Pprev[j], Breg[j]));
                float cb = dmn + mn;
                if (wreg[j] > 0.f) { acc += wreg[j] * cb; Breg[j] = cb; }
                Pprev[j] = cc;
            }
        }
#pragma unroll
        for (int off = 16; off; off >>= 1)
            acc += __shfl_xor_sync(0xffffffffu, acc, off);

        if (lane == 0) stcg_f32(&g_C[m * NN + n], acc);
    }
}

// ---------------- stage 5: terminal expectation ----------------------------
__global__ void __launch_bounds__(256) final_kernel(float* __restrict__ out) {
    int t = threadIdx.x;
    float v = g_fw[t] * g_C[(MM - 1) * NN + t];
#pragma unroll
    for (int off = 16; off; off >>= 1) v += __shfl_xor_sync(0xffffffffu, v, off);
    __shared__ float s[8];
    if ((t & 31) == 0) s[t >> 5] = v;
    __syncthreads();
    if (t < 8) {
        float z = s[t];
#pragma unroll
        for (int off = 4; off; off >>= 1) z += __shfl_xor_sync(0xffu, z, off);
        if (t == 0) out[0] = z;
    }
}

// ---------------- launch ----------------------------------------------------
extern "C" void kernel_launch(void* const* d_in, const int* in_sizes, int n_in,
                              void* d_out, int out_size) {
    const float* x = nullptr;
    const float* y = nullptr;
    const float* q = nullptr;
    for (int i = 0; i < n_in; i++) {
        if (in_sizes[i] == MM * DD)            x = (const float*)d_in[i];
        else if (in_sizes[i] == NN * DD)       y = (const float*)d_in[i];
        else if (in_sizes[i] == (NN + 1) * NN) q = (const float*)d_in[i];
    }
    float* out = (float*)d_out;

    init_kernel<<<(MM * NN + 255) / 256, 256>>>();

    dim3 dg(MM / 32, NN / 64);
    dist_kernel<<<dg, 256>>>(x, y);

    transpose_q<<<(NN * (NN + 1) + 255) / 256, 256>>>(q);
    scan_kernel<<<1, 320>>>();
    weights_kernel<<<NN * NN / 256, 256>>>(q);

    dp_kernel<<<NN, 32>>>();    // one warp per column, all-resident

    final_kernel<<<1, 256>>>(out);
}